// round 1
// baseline (speedup 1.0000x reference)
#include <cuda_runtime.h>
#include <math_constants.h>

#define B_ 8
#define C_ 256
#define N_ 2048
#define SCALE 0.0625f  // 1/sqrt(256)

// ---------------------------------------------------------------------------
// GEMM1: S[b,i,j] = SCALE * sum_c K[b,c,i] * Q[b,c,j]
// K,Q are [B, C, N] row-major over N. Output written into weights region.
// 128x128 tile, kchunk=8, 256 threads, 8x8 micro-tile per thread (4+4 split).
// ---------------------------------------------------------------------------
__global__ __launch_bounds__(256, 2)
void gemm1_kernel(const float* __restrict__ q, const float* __restrict__ k,
                  float* __restrict__ w)
{
    const int b  = blockIdx.z;
    const int i0 = blockIdx.y * 128;
    const int j0 = blockIdx.x * 128;

    const float* Kb = k + (size_t)b * C_ * N_;
    const float* Qb = q + (size_t)b * C_ * N_;
    float*       Wb = w + (size_t)b * N_ * N_;

    __shared__ float Ks[8][128];
    __shared__ float Qs[8][128];

    const int tid = threadIdx.x;
    const int lr  = tid >> 5;          // 0..7  (k-row for loads)
    const int lc  = tid & 31;          // float4 column
    const int ty  = tid >> 4;          // 0..15
    const int tx  = tid & 15;          // 0..15

    float acc[8][8];
#pragma unroll
    for (int u = 0; u < 8; u++)
#pragma unroll
        for (int v = 0; v < 8; v++) acc[u][v] = 0.f;

    for (int kc = 0; kc < C_; kc += 8) {
        __syncthreads();
        *(float4*)&Ks[lr][lc * 4] = *(const float4*)&Kb[(size_t)(kc + lr) * N_ + i0 + lc * 4];
        *(float4*)&Qs[lr][lc * 4] = *(const float4*)&Qb[(size_t)(kc + lr) * N_ + j0 + lc * 4];
        __syncthreads();

#pragma unroll
        for (int cc = 0; cc < 8; cc++) {
            float a[8], bb[8];
            *(float4*)&a[0]  = *(float4*)&Ks[cc][ty * 4];
            *(float4*)&a[4]  = *(float4*)&Ks[cc][64 + ty * 4];
            *(float4*)&bb[0] = *(float4*)&Qs[cc][tx * 4];
            *(float4*)&bb[4] = *(float4*)&Qs[cc][64 + tx * 4];
#pragma unroll
            for (int u = 0; u < 8; u++)
#pragma unroll
                for (int v = 0; v < 8; v++)
                    acc[u][v] = fmaf(a[u], bb[v], acc[u][v]);
        }
    }

    // write S * SCALE
#pragma unroll
    for (int u = 0; u < 8; u++) {
        const int ri = i0 + ((u < 4) ? (ty * 4 + u) : (64 + ty * 4 + (u - 4)));
        float4 lo = make_float4(acc[u][0] * SCALE, acc[u][1] * SCALE,
                                acc[u][2] * SCALE, acc[u][3] * SCALE);
        float4 hi = make_float4(acc[u][4] * SCALE, acc[u][5] * SCALE,
                                acc[u][6] * SCALE, acc[u][7] * SCALE);
        *(float4*)&Wb[(size_t)ri * N_ + j0 + tx * 4]      = lo;
        *(float4*)&Wb[(size_t)ri * N_ + j0 + 64 + tx * 4] = hi;
    }
}

// ---------------------------------------------------------------------------
// Column softmax (over i) of W[b, i, j], in place.
// Block: 512 threads = 64 columns x 8 segments of 256 rows each.
// Online (m,l) per segment, smem merge, then normalize pass.
// ---------------------------------------------------------------------------
__global__ __launch_bounds__(512, 2)
void softmax_kernel(float* __restrict__ w)
{
    const int b   = blockIdx.y;
    const int jl  = threadIdx.x & 63;
    const int seg = threadIdx.x >> 6;      // 0..7
    const int j   = blockIdx.x * 64 + jl;

    float* Wb = w + (size_t)b * N_ * N_;
    const int I0 = seg * 256;

    float m = -CUDART_INF_F, l = 0.f;
    for (int i = I0; i < I0 + 256; i += 8) {
        float x[8];
#pragma unroll
        for (int u = 0; u < 8; u++) x[u] = Wb[(size_t)(i + u) * N_ + j];
        float cm = x[0];
#pragma unroll
        for (int u = 1; u < 8; u++) cm = fmaxf(cm, x[u]);
        float cl = 0.f;
#pragma unroll
        for (int u = 0; u < 8; u++) cl += __expf(x[u] - cm);
        const float nm = fmaxf(m, cm);
        l = l * __expf(m - nm) + cl * __expf(cm - nm);
        m = nm;
    }

    __shared__ float sm[8][64];
    __shared__ float sl[8][64];
    sm[seg][jl] = m;
    sl[seg][jl] = l;
    __syncthreads();

    __shared__ float fm_s[64], fl_s[64];
    if (seg == 0) {
        float fm = sm[0][jl], fl = sl[0][jl];
#pragma unroll
        for (int s = 1; s < 8; s++) {
            const float om = sm[s][jl], ol = sl[s][jl];
            const float nm = fmaxf(fm, om);
            fl = fl * __expf(fm - nm) + ol * __expf(om - nm);
            fm = nm;
        }
        fm_s[jl] = fm;
        fl_s[jl] = fl;
    }
    __syncthreads();

    const float fm  = fm_s[jl];
    const float inv = 1.f / fl_s[jl];
    for (int i = I0; i < I0 + 256; i += 8) {
        float x[8];
#pragma unroll
        for (int u = 0; u < 8; u++) x[u] = Wb[(size_t)(i + u) * N_ + j];
#pragma unroll
        for (int u = 0; u < 8; u++) Wb[(size_t)(i + u) * N_ + j] = __expf(x[u] - fm) * inv;
    }
}

// ---------------------------------------------------------------------------
// GEMM2: out[b,c,j] = sum_i V[b,c,i] * W[b,i,j]
// 128x128 tile, kchunk=8, 256 threads, 8x8 per thread.
// ---------------------------------------------------------------------------
__global__ __launch_bounds__(256, 2)
void gemm2_kernel(const float* __restrict__ v, const float* __restrict__ w,
                  float* __restrict__ out)
{
    const int b  = blockIdx.z;
    const int m0 = blockIdx.y * 128;   // c
    const int j0 = blockIdx.x * 128;

    const float* Vb = v + (size_t)b * C_ * N_;
    const float* Wb = w + (size_t)b * N_ * N_;
    float*       Ob = out + (size_t)b * C_ * N_;

    __shared__ float Vs[8][128];   // [k][m] (transposed)
    __shared__ float Ws[8][128];   // [k][j]

    const int tid  = threadIdx.x;
    const int mm   = tid >> 1;         // 0..127 row of V tile
    const int quad = tid & 1;          // which float4 within 8 k's
    const int lr   = tid >> 5;
    const int lc   = tid & 31;
    const int ty   = tid >> 4;
    const int tx   = tid & 15;

    float acc[8][8];
#pragma unroll
    for (int u = 0; u < 8; u++)
#pragma unroll
        for (int vv = 0; vv < 8; vv++) acc[u][vv] = 0.f;

    for (int kc = 0; kc < N_; kc += 8) {
        __syncthreads();
        // V tile: transpose into Vs[k][m]
        float4 v4 = *(const float4*)&Vb[(size_t)(m0 + mm) * N_ + kc + quad * 4];
        Vs[quad * 4 + 0][mm] = v4.x;
        Vs[quad * 4 + 1][mm] = v4.y;
        Vs[quad * 4 + 2][mm] = v4.z;
        Vs[quad * 4 + 3][mm] = v4.w;
        // W tile
        *(float4*)&Ws[lr][lc * 4] = *(const float4*)&Wb[(size_t)(kc + lr) * N_ + j0 + lc * 4];
        __syncthreads();

#pragma unroll
        for (int cc = 0; cc < 8; cc++) {
            float a[8], bb[8];
            *(float4*)&a[0]  = *(float4*)&Vs[cc][ty * 4];
            *(float4*)&a[4]  = *(float4*)&Vs[cc][64 + ty * 4];
            *(float4*)&bb[0] = *(float4*)&Ws[cc][tx * 4];
            *(float4*)&bb[4] = *(float4*)&Ws[cc][64 + tx * 4];
#pragma unroll
            for (int u = 0; u < 8; u++)
#pragma unroll
                for (int vv = 0; vv < 8; vv++)
                    acc[u][vv] = fmaf(a[u], bb[vv], acc[u][vv]);
        }
    }

#pragma unroll
    for (int u = 0; u < 8; u++) {
        const int rc = m0 + ((u < 4) ? (ty * 4 + u) : (64 + ty * 4 + (u - 4)));
        *(float4*)&Ob[(size_t)rc * N_ + j0 + tx * 4]      = *(float4*)&acc[u][0];
        *(float4*)&Ob[(size_t)rc * N_ + j0 + 64 + tx * 4] = *(float4*)&acc[u][4];
    }
}

// ---------------------------------------------------------------------------
extern "C" void kernel_launch(void* const* d_in, const int* in_sizes, int n_in,
                              void* d_out, int out_size)
{
    const float* q = (const float*)d_in[0];
    const float* k = (const float*)d_in[1];
    const float* v = (const float*)d_in[2];

    float* out = (float*)d_out;                       // [B, C, N]
    float* w   = (float*)d_out + (size_t)B_ * C_ * N_; // [B, N, N] weights

    dim3 g1(N_ / 128, N_ / 128, B_);   // (16,16,8)
    gemm1_kernel<<<g1, 256>>>(q, k, w);

    dim3 gs(N_ / 64, B_);              // (32,8)
    softmax_kernel<<<gs, 512>>>(w);

    dim3 g2(N_ / 128, C_ / 128, B_);   // (16,2,8)
    gemm2_kernel<<<g2, 256>>>(v, w, out);
}

// round 3
// speedup vs baseline: 2.2994x; 2.2994x over previous
#include <cuda_runtime.h>
#include <math_constants.h>
#include <cstdint>

#define B_ 8
#define C_ 256
#define N_ 2048
#define SCALE 0.0625f  // 1/sqrt(256)

__device__ __forceinline__ float to_tf32(float x) {
    uint32_t u;
    asm("cvt.rna.tf32.f32 %0, %1;" : "=r"(u) : "f"(x));
    return __uint_as_float(u);
}

__device__ __forceinline__ void mma_tf32(float4& d, const uint32_t a[4],
                                         const uint32_t b[2]) {
    asm volatile(
        "mma.sync.aligned.m16n8k8.row.col.f32.tf32.tf32.f32 "
        "{%0,%1,%2,%3}, {%4,%5,%6,%7}, {%8,%9}, {%0,%1,%2,%3};"
        : "+f"(d.x), "+f"(d.y), "+f"(d.z), "+f"(d.w)
        : "r"(a[0]), "r"(a[1]), "r"(a[2]), "r"(a[3]), "r"(b[0]), "r"(b[1]));
}

// ============================================================================
// Unified batched GEMM via mma.sync (tf32):
//   D[b, m, j] = scale * sum_k A(b, k, m) * B(b, k, j)
// A_KCONTIG=false: A GMEM layout is [k][m] (m contiguous)  -> K and Q and W
// A_KCONTIG=true : A GMEM layout is [m][k] (k contiguous)  -> V
// All leading dims are N_ = 2048.
// CTA: 128x128 tile, 128 threads = 4 warps, warp tile 64x64.
// ============================================================================
template <bool A_KCONTIG, bool DO_SCALE>
__global__ __launch_bounds__(128, 2)
void mma_gemm(const float* __restrict__ Ag, const float* __restrict__ Bg,
              float* __restrict__ Dg, size_t strideA, size_t strideB,
              size_t strideD, int Ktot)
{
    __shared__ float As[2][16][136];
    __shared__ float Bs[2][16][136];

    const int tid  = threadIdx.x;
    const int w    = tid >> 5;
    const int lane = tid & 31;
    const int qr   = lane >> 2;   // 0..7
    const int qc   = lane & 3;    // 0..3
    const int wm   = (w >> 1) * 64;
    const int wn   = (w & 1) * 64;
    const int m0   = blockIdx.y * 128;
    const int j0   = blockIdx.x * 128;

    const float* A = Ag + (size_t)blockIdx.z * strideA;
    const float* Bp = Bg + (size_t)blockIdx.z * strideB;
    float*       Dp = Dg + (size_t)blockIdx.z * strideD;

    float4 acc[4][8];
#pragma unroll
    for (int mt = 0; mt < 4; mt++)
#pragma unroll
        for (int nt = 0; nt < 8; nt++)
            acc[mt][nt] = make_float4(0.f, 0.f, 0.f, 0.f);

    float4 ra[4], rb[4];
    const int kr = tid >> 5;   // 0..3 (T-load row group)

    // ---------------- loaders ----------------
    auto ldgA = [&](int k0) {
        if (A_KCONTIG) {
            const float* p = A + (size_t)(m0 + tid) * N_ + k0;
#pragma unroll
            for (int i = 0; i < 4; i++) ra[i] = *(const float4*)(p + i * 4);
        } else {
            const float* p = A + (size_t)(k0 + kr) * N_ + m0 + lane * 4;
#pragma unroll
            for (int i = 0; i < 4; i++)
                ra[i] = *(const float4*)(p + (size_t)i * 4 * N_);
        }
    };
    auto ldgB = [&](int k0) {
        const float* p = Bp + (size_t)(k0 + kr) * N_ + j0 + lane * 4;
#pragma unroll
        for (int i = 0; i < 4; i++)
            rb[i] = *(const float4*)(p + (size_t)i * 4 * N_);
    };
    auto stsA = [&](int buf) {
        if (A_KCONTIG) {
            const float* rf = (const float*)ra;
#pragma unroll
            for (int kk = 0; kk < 16; kk++)
                As[buf][kk][tid] = to_tf32(rf[kk]);
        } else {
#pragma unroll
            for (int i = 0; i < 4; i++) {
                float4 v = ra[i];
                v.x = to_tf32(v.x); v.y = to_tf32(v.y);
                v.z = to_tf32(v.z); v.w = to_tf32(v.w);
                *(float4*)&As[buf][i * 4 + kr][lane * 4] = v;
            }
        }
    };
    auto stsB = [&](int buf) {
#pragma unroll
        for (int i = 0; i < 4; i++) {
            float4 v = rb[i];
            v.x = to_tf32(v.x); v.y = to_tf32(v.y);
            v.z = to_tf32(v.z); v.w = to_tf32(v.w);
            *(float4*)&Bs[buf][i * 4 + kr][lane * 4] = v;
        }
    };

    // ---------------- mainloop ----------------
    const int S = Ktot >> 4;
    ldgA(0); ldgB(0);
    stsA(0); stsB(0);
    __syncthreads();

#pragma unroll 1
    for (int s = 0; s < S; s++) {
        const int buf = s & 1;
        if (s + 1 < S) { ldgA((s + 1) << 4); ldgB((s + 1) << 4); }

#pragma unroll
        for (int g = 0; g < 2; g++) {
            uint32_t af[4][4];
#pragma unroll
            for (int mt = 0; mt < 4; mt++) {
                const int r = wm + mt * 16 + qr;
                af[mt][0] = __float_as_uint(As[buf][g * 8 + qc][r]);
                af[mt][1] = __float_as_uint(As[buf][g * 8 + qc][r + 8]);
                af[mt][2] = __float_as_uint(As[buf][g * 8 + qc + 4][r]);
                af[mt][3] = __float_as_uint(As[buf][g * 8 + qc + 4][r + 8]);
            }
#pragma unroll
            for (int nt = 0; nt < 8; nt++) {
                uint32_t bf[2];
                const int cb = wn + nt * 8 + qr;
                bf[0] = __float_as_uint(Bs[buf][g * 8 + qc][cb]);
                bf[1] = __float_as_uint(Bs[buf][g * 8 + qc + 4][cb]);
#pragma unroll
                for (int mt = 0; mt < 4; mt++)
                    mma_tf32(acc[mt][nt], af[mt], bf);
            }
        }

        if (s + 1 < S) {
            stsA(buf ^ 1); stsB(buf ^ 1);
            __syncthreads();
        }
    }

    // ---------------- epilogue ----------------
    const float sc = DO_SCALE ? SCALE : 1.0f;
#pragma unroll
    for (int mt = 0; mt < 4; mt++) {
        const int r0 = m0 + wm + mt * 16 + qr;
#pragma unroll
        for (int nt = 0; nt < 8; nt++) {
            const int c0 = j0 + wn + nt * 8 + qc * 2;
            float2 v0 = make_float2(acc[mt][nt].x * sc, acc[mt][nt].y * sc);
            float2 v1 = make_float2(acc[mt][nt].z * sc, acc[mt][nt].w * sc);
            *(float2*)&Dp[(size_t)r0 * N_ + c0]       = v0;
            *(float2*)&Dp[(size_t)(r0 + 8) * N_ + c0] = v1;
        }
    }
}

// ============================================================================
// Softmax over i (axis=1) of W[b,i,j], in place.
// ============================================================================
__global__ __launch_bounds__(512, 2)
void softmax_kernel(float* __restrict__ w)
{
    const int b   = blockIdx.y;
    const int jl  = threadIdx.x & 63;
    const int seg = threadIdx.x >> 6;
    const int j   = blockIdx.x * 64 + jl;

    float* Wb = w + (size_t)b * N_ * N_;
    const int I0 = seg * 256;

    float m = -CUDART_INF_F, l = 0.f;
    for (int i = I0; i < I0 + 256; i += 8) {
        float x[8];
#pragma unroll
        for (int u = 0; u < 8; u++) x[u] = Wb[(size_t)(i + u) * N_ + j];
        float cm = x[0];
#pragma unroll
        for (int u = 1; u < 8; u++) cm = fmaxf(cm, x[u]);
        float cl = 0.f;
#pragma unroll
        for (int u = 0; u < 8; u++) cl += __expf(x[u] - cm);
        const float nm = fmaxf(m, cm);
        l = l * __expf(m - nm) + cl * __expf(cm - nm);
        m = nm;
    }

    __shared__ float sm[8][64];
    __shared__ float sl[8][64];
    sm[seg][jl] = m;
    sl[seg][jl] = l;
    __syncthreads();

    __shared__ float fm_s[64], fl_s[64];
    if (seg == 0) {
        float fm = sm[0][jl], fl = sl[0][jl];
#pragma unroll
        for (int s = 1; s < 8; s++) {
            const float om = sm[s][jl], ol = sl[s][jl];
            const float nm = fmaxf(fm, om);
            fl = fl * __expf(fm - nm) + ol * __expf(om - nm);
            fm = nm;
        }
        fm_s[jl] = fm;
        fl_s[jl] = fl;
    }
    __syncthreads();

    const float fm  = fm_s[jl];
    const float inv = 1.f / fl_s[jl];
    for (int i = I0; i < I0 + 256; i += 8) {
        float x[8];
#pragma unroll
        for (int u = 0; u < 8; u++) x[u] = Wb[(size_t)(i + u) * N_ + j];
#pragma unroll
        for (int u = 0; u < 8; u++) Wb[(size_t)(i + u) * N_ + j] = __expf(x[u] - fm) * inv;
    }
}

// ============================================================================
extern "C" void kernel_launch(void* const* d_in, const int* in_sizes, int n_in,
                              void* d_out, int out_size)
{
    const float* q = (const float*)d_in[0];
    const float* k = (const float*)d_in[1];
    const float* v = (const float*)d_in[2];

    float* out = (float*)d_out;                        // [B, C, N]
    float* w   = (float*)d_out + (size_t)B_ * C_ * N_; // [B, N, N]

    const size_t CN = (size_t)C_ * N_;
    const size_t NN = (size_t)N_ * N_;

    // GEMM1: W[i,j] = SCALE * sum_c K[c,i] Q[c,j]   (A = K, T-load)
    dim3 g1(N_ / 128, N_ / 128, B_);   // (16,16,8)
    mma_gemm<false, true><<<g1, 128>>>(k, q, w, CN, CN, NN, C_);

    // softmax over i
    dim3 gs(N_ / 64, B_);              // (32,8)
    softmax_kernel<<<gs, 512>>>(w);

    // GEMM2: out[c,j] = sum_i V[c,i] W[i,j]         (A = V, k-contiguous)
    dim3 g2(N_ / 128, C_ / 128, B_);   // (16,2,8)
    mma_gemm<true, false><<<g2, 128>>>(v, w, out, CN, NN, CN, N_);
}

// round 4
// speedup vs baseline: 2.4171x; 1.0512x over previous
#include <cuda_runtime.h>
#include <math_constants.h>
#include <cstdint>

#define B_ 8
#define C_ 256
#define N_ 2048
#define SCALE 0.0625f  // 1/sqrt(256)

__device__ __forceinline__ float to_tf32(float x) {
    uint32_t u;
    asm("cvt.rna.tf32.f32 %0, %1;" : "=r"(u) : "f"(x));
    return __uint_as_float(u);
}

__device__ __forceinline__ void mma_tf32(float4& d, const uint32_t a[4],
                                         const uint32_t b[2]) {
    asm volatile(
        "mma.sync.aligned.m16n8k8.row.col.f32.tf32.tf32.f32 "
        "{%0,%1,%2,%3}, {%4,%5,%6,%7}, {%8,%9}, {%0,%1,%2,%3};"
        : "+f"(d.x), "+f"(d.y), "+f"(d.z), "+f"(d.w)
        : "r"(a[0]), "r"(a[1]), "r"(a[2]), "r"(a[3]), "r"(b[0]), "r"(b[1]));
}

// ============================================================================
// Batched GEMM via mma.sync (tf32):  D[b,m,j] = scale * sum_k A(b,k,m)*B(b,k,j)
// A_KCONTIG=false: A GMEM layout [k][m] (m contiguous)  -> K (gemm1)
// A_KCONTIG=true : A GMEM layout [m][k] (k contiguous)  -> V (gemm2)
// CTA: 128x128 tile, 256 threads = 8 warps (2x4), warp tile 64x32, BK=16.
// ============================================================================
template <bool A_KCONTIG, bool DO_SCALE>
__global__ __launch_bounds__(256, 2)
void mma_gemm(const float* __restrict__ Ag, const float* __restrict__ Bg,
              float* __restrict__ Dg, size_t strideA, size_t strideB,
              size_t strideD, int Ktot)
{
    __shared__ float As[2][16][136];
    __shared__ float Bs[2][16][136];

    const int tid  = threadIdx.x;
    const int w    = tid >> 5;
    const int lane = tid & 31;
    const int qr   = lane >> 2;   // 0..7
    const int qc   = lane & 3;    // 0..3
    const int wm   = (w >> 2) * 64;   // 2 warp-rows
    const int wn   = (w & 3) * 32;    // 4 warp-cols
    const int m0   = blockIdx.y * 128;
    const int j0   = blockIdx.x * 128;

    const float* A  = Ag + (size_t)blockIdx.z * strideA;
    const float* Bp = Bg + (size_t)blockIdx.z * strideB;
    float*       Dp = Dg + (size_t)blockIdx.z * strideD;

    float4 acc[4][4];
#pragma unroll
    for (int mt = 0; mt < 4; mt++)
#pragma unroll
        for (int nt = 0; nt < 4; nt++)
            acc[mt][nt] = make_float4(0.f, 0.f, 0.f, 0.f);

    float4 ra[2], rb[2];
    const int kr8 = tid >> 5;    // 0..7 (k-row group for row-major loads)
    const int lc  = lane;        // float4 column 0..31

    // ---------------- loaders ----------------
    auto ldgA = [&](int k0) {
        if (A_KCONTIG) {
            // thread -> (m = tid>>1, k-quad = tid&1), 2 float4 along k
            const float* p = A + (size_t)(m0 + (tid >> 1)) * N_ + k0 + (tid & 1) * 8;
            ra[0] = *(const float4*)(p);
            ra[1] = *(const float4*)(p + 4);
        } else {
            const float* p = A + (size_t)(k0 + kr8) * N_ + m0 + lc * 4;
            ra[0] = *(const float4*)(p);
            ra[1] = *(const float4*)(p + (size_t)8 * N_);
        }
    };
    auto ldgB = [&](int k0) {
        const float* p = Bp + (size_t)(k0 + kr8) * N_ + j0 + lc * 4;
        rb[0] = *(const float4*)(p);
        rb[1] = *(const float4*)(p + (size_t)8 * N_);
    };
    auto stsA = [&](int buf) {
        if (A_KCONTIG) {
            const int mrow = tid >> 1, kq = (tid & 1) * 8;
            const float* rf = (const float*)ra;
#pragma unroll
            for (int t = 0; t < 8; t++)
                As[buf][kq + t][mrow] = to_tf32(rf[t]);
        } else {
#pragma unroll
            for (int i = 0; i < 2; i++) {
                float4 v = ra[i];
                v.x = to_tf32(v.x); v.y = to_tf32(v.y);
                v.z = to_tf32(v.z); v.w = to_tf32(v.w);
                *(float4*)&As[buf][kr8 + i * 8][lc * 4] = v;
            }
        }
    };
    auto stsB = [&](int buf) {
#pragma unroll
        for (int i = 0; i < 2; i++) {
            float4 v = rb[i];
            v.x = to_tf32(v.x); v.y = to_tf32(v.y);
            v.z = to_tf32(v.z); v.w = to_tf32(v.w);
            *(float4*)&Bs[buf][kr8 + i * 8][lc * 4] = v;
        }
    };

    // ---------------- mainloop ----------------
    const int S = Ktot >> 4;
    ldgA(0); ldgB(0);
    stsA(0); stsB(0);
    __syncthreads();

#pragma unroll 1
    for (int s = 0; s < S; s++) {
        const int buf = s & 1;
        if (s + 1 < S) { ldgA((s + 1) << 4); ldgB((s + 1) << 4); }

#pragma unroll
        for (int g = 0; g < 2; g++) {
            uint32_t af[4][4];
#pragma unroll
            for (int mt = 0; mt < 4; mt++) {
                const int r = wm + mt * 16 + qr;
                af[mt][0] = __float_as_uint(As[buf][g * 8 + qc][r]);
                af[mt][1] = __float_as_uint(As[buf][g * 8 + qc][r + 8]);
                af[mt][2] = __float_as_uint(As[buf][g * 8 + qc + 4][r]);
                af[mt][3] = __float_as_uint(As[buf][g * 8 + qc + 4][r + 8]);
            }
#pragma unroll
            for (int nt = 0; nt < 4; nt++) {
                uint32_t bf[2];
                const int cb = wn + nt * 8 + qr;
                bf[0] = __float_as_uint(Bs[buf][g * 8 + qc][cb]);
                bf[1] = __float_as_uint(Bs[buf][g * 8 + qc + 4][cb]);
#pragma unroll
                for (int mt = 0; mt < 4; mt++)
                    mma_tf32(acc[mt][nt], af[mt], bf);
            }
        }

        if (s + 1 < S) {
            stsA(buf ^ 1); stsB(buf ^ 1);
            __syncthreads();
        }
    }

    // ---------------- epilogue ----------------
    const float sc = DO_SCALE ? SCALE : 1.0f;
#pragma unroll
    for (int mt = 0; mt < 4; mt++) {
        const int r0 = m0 + wm + mt * 16 + qr;
#pragma unroll
        for (int nt = 0; nt < 4; nt++) {
            const int c0 = j0 + wn + nt * 8 + qc * 2;
            float2 v0 = make_float2(acc[mt][nt].x * sc, acc[mt][nt].y * sc);
            float2 v1 = make_float2(acc[mt][nt].z * sc, acc[mt][nt].w * sc);
            *(float2*)&Dp[(size_t)r0 * N_ + c0]       = v0;
            *(float2*)&Dp[(size_t)(r0 + 8) * N_ + c0] = v1;
        }
    }
}

// ============================================================================
// Softmax over i (axis=1) of W[b,i,j], in place.
// ============================================================================
__global__ __launch_bounds__(512, 2)
void softmax_kernel(float* __restrict__ w)
{
    const int b   = blockIdx.y;
    const int jl  = threadIdx.x & 63;
    const int seg = threadIdx.x >> 6;
    const int j   = blockIdx.x * 64 + jl;

    float* Wb = w + (size_t)b * N_ * N_;
    const int I0 = seg * 256;

    float m = -CUDART_INF_F, l = 0.f;
    for (int i = I0; i < I0 + 256; i += 8) {
        float x[8];
#pragma unroll
        for (int u = 0; u < 8; u++) x[u] = Wb[(size_t)(i + u) * N_ + j];
        float cm = x[0];
#pragma unroll
        for (int u = 1; u < 8; u++) cm = fmaxf(cm, x[u]);
        float cl = 0.f;
#pragma unroll
        for (int u = 0; u < 8; u++) cl += __expf(x[u] - cm);
        const float nm = fmaxf(m, cm);
        l = l * __expf(m - nm) + cl * __expf(cm - nm);
        m = nm;
    }

    __shared__ float sm[8][64];
    __shared__ float sl[8][64];
    sm[seg][jl] = m;
    sl[seg][jl] = l;
    __syncthreads();

    __shared__ float fm_s[64], fl_s[64];
    if (seg == 0) {
        float fm = sm[0][jl], fl = sl[0][jl];
#pragma unroll
        for (int s = 1; s < 8; s++) {
            const float om = sm[s][jl], ol = sl[s][jl];
            const float nm = fmaxf(fm, om);
            fl = fl * __expf(fm - nm) + ol * __expf(om - nm);
            fm = nm;
        }
        fm_s[jl] = fm;
        fl_s[jl] = fl;
    }
    __syncthreads();

    const float fm  = fm_s[jl];
    const float inv = 1.f / fl_s[jl];
    for (int i = I0; i < I0 + 256; i += 8) {
        float x[8];
#pragma unroll
        for (int u = 0; u < 8; u++) x[u] = Wb[(size_t)(i + u) * N_ + j];
#pragma unroll
        for (int u = 0; u < 8; u++) Wb[(size_t)(i + u) * N_ + j] = __expf(x[u] - fm) * inv;
    }
}

// ============================================================================
extern "C" void kernel_launch(void* const* d_in, const int* in_sizes, int n_in,
                              void* d_out, int out_size)
{
    const float* q = (const float*)d_in[0];
    const float* k = (const float*)d_in[1];
    const float* v = (const float*)d_in[2];

    float* out = (float*)d_out;                        // [B, C, N]
    float* w   = (float*)d_out + (size_t)B_ * C_ * N_; // [B, N, N]

    const size_t CN = (size_t)C_ * N_;
    const size_t NN = (size_t)N_ * N_;

    // GEMM1: W[i,j] = SCALE * sum_c K[c,i] Q[c,j]
    dim3 g1(N_ / 128, N_ / 128, B_);   // (16,16,8)
    mma_gemm<false, true><<<g1, 256>>>(k, q, w, CN, CN, NN, C_);

    // softmax over i
    dim3 gs(N_ / 64, B_);              // (32,8)
    softmax_kernel<<<gs, 512>>>(w);

    // GEMM2: out[c,j] = sum_i V[c,i] W[i,j]
    dim3 g2(N_ / 128, C_ / 128, B_);   // (16,2,8)
    mma_gemm<true, false><<<g2, 256>>>(v, w, out, CN, NN, CN, N_);
}